// round 1
// baseline (speedup 1.0000x reference)
#include <cuda_runtime.h>
#include <cuda_bf16.h>

#define NMAX 100000
#define D 64

// Scratch (allocation-free: __device__ globals)
__device__ float g_h[NMAX * D];     // matmul output / gather source
__device__ float g_agg[NMAX * D];   // scatter destination
__device__ float g_y[NMAX * D];     // layer output (post relu)
__device__ float g_deg[NMAX];
__device__ float g_dinv[NMAX];
__device__ float g_sums[D];

// ---------------------------------------------------------------------------
__global__ void zero_deg_k(int n) {
    int i = blockIdx.x * blockDim.x + threadIdx.x;
    if (i < n) g_deg[i] = 0.0f;
}

__global__ void zero_sums_k() {
    if (threadIdx.x < D) g_sums[threadIdx.x] = 0.0f;
}

__global__ void degree_k(const int* __restrict__ dst, int E) {
    int i = blockIdx.x * blockDim.x + threadIdx.x;
    if (i < E) atomicAdd(&g_deg[dst[i]], 1.0f);
}

__global__ void dinv_k(int n) {
    int i = blockIdx.x * blockDim.x + threadIdx.x;
    if (i < n) g_dinv[i] = rsqrtf(g_deg[i] + 1.0f);  // +1 = self loop
}

// h = x @ W   (x: [n,64], W: [64,64])  — W staged in smem, x row in registers.
// use_y: read input from g_y (layer 2) instead of the x pointer.
__global__ void matmul_k(const float* __restrict__ x, const float* __restrict__ W,
                         int use_y, int n) {
    __shared__ float4 Ws[64 * 16];  // W rows as 16 float4 each
    for (int i = threadIdx.x; i < 64 * 16; i += blockDim.x)
        Ws[i] = reinterpret_cast<const float4*>(W)[i];
    __syncthreads();

    int row = blockIdx.x * blockDim.x + threadIdx.x;
    if (row >= n) return;

    const float* xin = use_y ? g_y : x;
    float xr[64];
    const float4* xv = reinterpret_cast<const float4*>(xin + (size_t)row * D);
#pragma unroll
    for (int k = 0; k < 16; k++) {
        float4 t = xv[k];
        xr[4 * k + 0] = t.x; xr[4 * k + 1] = t.y;
        xr[4 * k + 2] = t.z; xr[4 * k + 3] = t.w;
    }

    float4* hv = reinterpret_cast<float4*>(g_h + (size_t)row * D);
#pragma unroll
    for (int jb = 0; jb < 16; jb++) {
        float4 acc = make_float4(0.f, 0.f, 0.f, 0.f);
#pragma unroll 16
        for (int k = 0; k < 64; k++) {
            float4 w = Ws[k * 16 + jb];   // broadcast LDS.128 across warp
            float xk = xr[k];
            acc.x += xk * w.x; acc.y += xk * w.y;
            acc.z += xk * w.z; acc.w += xk * w.w;
        }
        hv[jb] = acc;
    }
}

// agg[i] = h[i] * dinv[i]^2   (self-loop message; also serves as the zero-init)
__global__ void selfloop_init_k(int n) {
    int idx = blockIdx.x * blockDim.x + threadIdx.x;  // over n*16 float4s
    if (idx >= n * 16) return;
    int row = idx >> 4;
    float dv = g_dinv[row];
    float nn = dv * dv;
    float4 v = reinterpret_cast<const float4*>(g_h)[idx];
    v.x *= nn; v.y *= nn; v.z *= nn; v.w *= nn;
    reinterpret_cast<float4*>(g_agg)[idx] = v;
}

// 16 threads per edge; each does one float4 gather + one red.global.add.v4.f32
__global__ void scatter_k(const int* __restrict__ src, const int* __restrict__ dst, int E) {
    int t = blockIdx.x * blockDim.x + threadIdx.x;
    int e = t >> 4;
    if (e >= E) return;
    int lane = t & 15;
    int s = src[e];
    int d = dst[e];
    float norm = g_dinv[s] * g_dinv[d];
    float4 v = reinterpret_cast<const float4*>(g_h)[s * 16 + lane];
    v.x *= norm; v.y *= norm; v.z *= norm; v.w *= norm;
    float* addr = g_agg + ((size_t)d * D + lane * 4);
    asm volatile("red.global.add.v4.f32 [%0], {%1,%2,%3,%4};"
                 :: "l"(addr), "f"(v.x), "f"(v.y), "f"(v.z), "f"(v.w)
                 : "memory");
}

// y = relu(agg + b)
__global__ void bias_relu_k(const float* __restrict__ b, int n) {
    int idx = blockIdx.x * blockDim.x + threadIdx.x;  // over n*16 float4s
    if (idx >= n * 16) return;
    int jb = idx & 15;
    float4 bb = reinterpret_cast<const float4*>(b)[jb];
    float4 v = reinterpret_cast<const float4*>(g_agg)[idx];
    v.x = fmaxf(v.x + bb.x, 0.f);
    v.y = fmaxf(v.y + bb.y, 0.f);
    v.z = fmaxf(v.z + bb.z, 0.f);
    v.w = fmaxf(v.w + bb.w, 0.f);
    reinterpret_cast<float4*>(g_y)[idx] = v;
}

// column sums of g_y into g_sums[64]
__global__ void pool_k(int n) {
    __shared__ float s[D];
    if (threadIdx.x < D) s[threadIdx.x] = 0.0f;
    __syncthreads();
    float local = 0.0f;
    int total = n * D;
    int stride = gridDim.x * blockDim.x;  // multiple of 64
    for (int i = blockIdx.x * blockDim.x + threadIdx.x; i < total; i += stride)
        local += g_y[i];
    atomicAdd(&s[threadIdx.x & 63], local);
    __syncthreads();
    if (threadIdx.x < D) atomicAdd(&g_sums[threadIdx.x], s[threadIdx.x]);
}

// out[j] = fc_b[j] + sum_k mean[k] * fc_w[j,k]
__global__ void fc_k(const float* __restrict__ fcw, const float* __restrict__ fcb,
                     float* __restrict__ out, float invn) {
    int j = threadIdx.x;
    if (j >= D) return;
    float acc = fcb[j];
#pragma unroll 16
    for (int k = 0; k < D; k++)
        acc += (g_sums[k] * invn) * fcw[j * D + k];
    out[j] = acc;
}

// ---------------------------------------------------------------------------
static void run_graph(const float* x, const int* ei, int E, int n,
                      const float* W1, const float* b1,
                      const float* W2, const float* b2,
                      const float* fcw, const float* fcb, float* out) {
    const int* src = ei;
    const int* dst = ei + E;
    const int T = 256;
    int nBlk = (n + T - 1) / T;
    int eBlk = (E + T - 1) / T;
    int vBlk = (n * 16 + T - 1) / T;       // n*16 float4 elements
    int sBlk = ((E * 16) + T - 1) / T;     // 16 threads per edge

    // normalization
    zero_deg_k<<<nBlk, T>>>(n);
    degree_k<<<eBlk, T>>>(dst, E);
    dinv_k<<<nBlk, T>>>(n);

    // layer 1
    matmul_k<<<nBlk, T>>>(x, W1, 0, n);
    selfloop_init_k<<<vBlk, T>>>(n);
    scatter_k<<<sBlk, T>>>(src, dst, E);
    bias_relu_k<<<vBlk, T>>>(b1, n);

    // layer 2 (input = g_y)
    matmul_k<<<nBlk, T>>>(x, W2, 1, n);
    selfloop_init_k<<<vBlk, T>>>(n);
    scatter_k<<<sBlk, T>>>(src, dst, E);
    bias_relu_k<<<vBlk, T>>>(b2, n);

    // mean pool + fc
    zero_sums_k<<<1, 64>>>();
    pool_k<<<512, T>>>(n);
    fc_k<<<1, 64>>>(fcw, fcb, out, 1.0f / (float)n);
}

extern "C" void kernel_launch(void* const* d_in, const int* in_sizes, int n_in,
                              void* d_out, int out_size) {
    const float* x1  = (const float*)d_in[0];
    const float* x2  = (const float*)d_in[1];
    const int*   e1  = (const int*)d_in[2];
    const int*   e2  = (const int*)d_in[3];
    const float* W1  = (const float*)d_in[4];
    const float* b1  = (const float*)d_in[5];
    const float* W2  = (const float*)d_in[6];
    const float* b2  = (const float*)d_in[7];
    const float* fcw = (const float*)d_in[8];
    const float* fcb = (const float*)d_in[9];

    int n  = in_sizes[0] / D;
    int E1 = in_sizes[2] / 2;
    int E2 = in_sizes[3] / 2;
    float* out = (float*)d_out;

    run_graph(x1, e1, E1, n, W1, b1, W2, b2, fcw, fcb, out);
    run_graph(x2, e2, E2, n, W1, b1, W2, b2, fcw, fcb, out + D);
}

// round 3
// speedup vs baseline: 1.0965x; 1.0965x over previous
#include <cuda_runtime.h>
#include <cuda_bf16.h>

#define NMAX 100000
#define EMAX 1700000
#define D 64

// Scratch (allocation-free: __device__ globals)
__device__ float g_h[NMAX * D];      // matmul output / gather source
__device__ float g_y[NMAX * D];      // layer output (post relu)
__device__ int   g_degi[NMAX];
__device__ float g_dinv[NMAX];
__device__ int   g_rowptr[NMAX + 1];
__device__ int   g_cnt[NMAX];
__device__ int   g_col[EMAX];
__device__ int   g_bsum[128];
__device__ int   g_boff[128];
__device__ float g_sums[D];

// ---------------------------------------------------------------------------
__global__ void zero_k(int n) {
    int i = blockIdx.x * blockDim.x + threadIdx.x;
    if (i < n) g_degi[i] = 0;
    if (i < D) g_sums[i] = 0.0f;
}

__global__ void degree_k(const int* __restrict__ dst, int E) {
    int i = blockIdx.x * blockDim.x + threadIdx.x;
    if (i < E) atomicAdd(&g_degi[dst[i]], 1);
}

__global__ void dinv_k(int n) {
    int i = blockIdx.x * blockDim.x + threadIdx.x;
    if (i < n) g_dinv[i] = rsqrtf((float)g_degi[i] + 1.0f);  // +1 = self loop
}

// ---- exclusive prefix scan of g_degi -> g_rowptr (3 kernels) ---------------
__global__ void scan_block_k(int n) {
    __shared__ int s[1024];
    int gid = blockIdx.x * 1024 + threadIdx.x;
    int v = (gid < n) ? g_degi[gid] : 0;
    s[threadIdx.x] = v;
    __syncthreads();
#pragma unroll
    for (int off = 1; off < 1024; off <<= 1) {
        int t = 0;
        if (threadIdx.x >= off) t = s[threadIdx.x - off];
        __syncthreads();
        if (threadIdx.x >= off) s[threadIdx.x] += t;
        __syncthreads();
    }
    if (gid < n) g_rowptr[gid] = s[threadIdx.x] - v;  // exclusive
    if (threadIdx.x == 1023) g_bsum[blockIdx.x] = s[1023];
}

__global__ void scan_bsums_k(int nb) {
    __shared__ int s[128];
    int v = (threadIdx.x < nb) ? g_bsum[threadIdx.x] : 0;
    s[threadIdx.x] = v;
    __syncthreads();
#pragma unroll
    for (int off = 1; off < 128; off <<= 1) {
        int t = 0;
        if (threadIdx.x >= off) t = s[threadIdx.x - off];
        __syncthreads();
        if (threadIdx.x >= off) s[threadIdx.x] += t;
        __syncthreads();
    }
    g_boff[threadIdx.x] = s[threadIdx.x] - v;  // exclusive
}

__global__ void add_off_k(int n, int E) {
    int gid = blockIdx.x * blockDim.x + threadIdx.x;
    if (gid < n) {
        g_rowptr[gid] += g_boff[gid >> 10];
        g_cnt[gid] = 0;
    }
    if (gid == n) g_rowptr[n] = E;
}

__global__ void fill_k(const int* __restrict__ src, const int* __restrict__ dst, int E) {
    int e = blockIdx.x * blockDim.x + threadIdx.x;
    if (e >= E) return;
    int s = src[e];
    int d = dst[e];
    int slot = g_rowptr[d] + atomicAdd(&g_cnt[d], 1);
    g_col[slot] = s;
}

// ---------------------------------------------------------------------------
// h = in @ W.  W[:,j] in 64 registers per thread (j = tid&63); x row read via
// broadcast LDG.128 (all 64 j-threads hit the same address -> one L1 request).
#define RPB 64
__global__ void matmul_k(const float* __restrict__ x, const float* __restrict__ W,
                         int use_y, int n) {
    int j = threadIdx.x & 63;
    int rg = threadIdx.x >> 6;  // 0..3
    const float* xin = use_y ? g_y : x;

    float w[64];
#pragma unroll
    for (int k = 0; k < 64; k++) w[k] = W[k * 64 + j];  // coalesced over j

    int rend = min((blockIdx.x + 1) * RPB, n);
    for (int r = blockIdx.x * RPB + rg; r < rend; r += 4) {
        const float4* xv = reinterpret_cast<const float4*>(xin + (size_t)r * D);
        float acc = 0.0f;
#pragma unroll
        for (int k4 = 0; k4 < 16; k4++) {
            float4 t = xv[k4];
            acc += t.x * w[4 * k4 + 0];
            acc += t.y * w[4 * k4 + 1];
            acc += t.z * w[4 * k4 + 2];
            acc += t.w * w[4 * k4 + 3];
        }
        g_h[(size_t)r * D + j] = acc;
    }
}

// ---------------------------------------------------------------------------
// Fused: y[d] = relu(b + dinv[d]^2 * h[d] + sum_nb dinv[s]*dinv[d] * h[s])
// 16 lanes per node, register accumulation, no atomics in neighbor loop.
// do_pool: also accumulate column sums (mean-pool) into g_sums.
__global__ void aggregate_k(const float* __restrict__ b, int n, int do_pool) {
    __shared__ float s[64];
    int tid = threadIdx.x;
    if (do_pool) {
        if (tid < 64) s[tid] = 0.0f;
        __syncthreads();
    }

    int row = blockIdx.x * 16 + (tid >> 4);
    int lane = tid & 15;
    float4 y = make_float4(0.f, 0.f, 0.f, 0.f);

    if (row < n) {
        const float4* hv = reinterpret_cast<const float4*>(g_h);
        float dd = g_dinv[row];
        float4 hself = hv[row * 16 + lane];
        float nself = dd * dd;
        float4 acc;
        acc.x = hself.x * nself; acc.y = hself.y * nself;
        acc.z = hself.z * nself; acc.w = hself.w * nself;

        int p0 = g_rowptr[row];
        int p1 = g_rowptr[row + 1];
        int s_next = (p0 < p1) ? g_col[p0] : 0;
        for (int p = p0; p < p1; p++) {
            int sidx = s_next;
            if (p + 1 < p1) s_next = g_col[p + 1];
            float nm = dd * g_dinv[sidx];
            float4 v = hv[sidx * 16 + lane];
            acc.x += v.x * nm; acc.y += v.y * nm;
            acc.z += v.z * nm; acc.w += v.w * nm;
        }

        float4 bb = reinterpret_cast<const float4*>(b)[lane];
        y.x = fmaxf(acc.x + bb.x, 0.f);
        y.y = fmaxf(acc.y + bb.y, 0.f);
        y.z = fmaxf(acc.z + bb.z, 0.f);
        y.w = fmaxf(acc.w + bb.w, 0.f);
        reinterpret_cast<float4*>(g_y)[row * 16 + lane] = y;
    }

    if (do_pool) {
        atomicAdd(&s[lane * 4 + 0], y.x);
        atomicAdd(&s[lane * 4 + 1], y.y);
        atomicAdd(&s[lane * 4 + 2], y.z);
        atomicAdd(&s[lane * 4 + 3], y.w);
        __syncthreads();
        if (tid < 64) atomicAdd(&g_sums[tid], s[tid]);
    }
}

// out[j] = fc_b[j] + sum_k mean[k] * fc_w[j,k]
__global__ void fc_k(const float* __restrict__ fcw, const float* __restrict__ fcb,
                     float* __restrict__ out, float invn) {
    int j = threadIdx.x;
    if (j >= D) return;
    float acc = fcb[j];
#pragma unroll 16
    for (int k = 0; k < D; k++)
        acc += (g_sums[k] * invn) * fcw[j * D + k];
    out[j] = acc;
}

// ---------------------------------------------------------------------------
static void run_graph(const float* x, const int* ei, int E, int n,
                      const float* W1, const float* b1,
                      const float* W2, const float* b2,
                      const float* fcw, const float* fcb, float* out) {
    const int* src = ei;
    const int* dst = ei + E;
    const int T = 256;
    int nBlk = (n + T - 1) / T;
    int eBlk = (E + T - 1) / T;
    int scanBlk = (n + 1023) / 1024;
    int aggBlk = (n + 15) / 16;

    // degree + normalization + CSR (built once, reused by both layers)
    zero_k<<<nBlk, T>>>(n);
    degree_k<<<eBlk, T>>>(dst, E);
    dinv_k<<<nBlk, T>>>(n);
    scan_block_k<<<scanBlk, 1024>>>(n);
    scan_bsums_k<<<1, 128>>>(scanBlk);
    add_off_k<<<(n + T) / T, T>>>(n, E);
    fill_k<<<eBlk, T>>>(src, dst, E);

    // layer 1
    matmul_k<<<(n + RPB - 1) / RPB, T>>>(x, W1, 0, n);
    aggregate_k<<<aggBlk, T>>>(b1, n, 0);

    // layer 2 (input = g_y); aggregation also does the mean-pool reduction
    matmul_k<<<(n + RPB - 1) / RPB, T>>>(x, W2, 1, n);
    aggregate_k<<<aggBlk, T>>>(b2, n, 1);

    fc_k<<<1, 64>>>(fcw, fcb, out, 1.0f / (float)n);
}

extern "C" void kernel_launch(void* const* d_in, const int* in_sizes, int n_in,
                              void* d_out, int out_size) {
    const float* x1  = (const float*)d_in[0];
    const float* x2  = (const float*)d_in[1];
    const int*   e1  = (const int*)d_in[2];
    const int*   e2  = (const int*)d_in[3];
    const float* W1  = (const float*)d_in[4];
    const float* b1  = (const float*)d_in[5];
    const float* W2  = (const float*)d_in[6];
    const float* b2  = (const float*)d_in[7];
    const float* fcw = (const float*)d_in[8];
    const float* fcb = (const float*)d_in[9];

    int n  = in_sizes[0] / D;
    int E1 = in_sizes[2] / 2;
    int E2 = in_sizes[3] / 2;
    float* out = (float*)d_out;

    run_graph(x1, e1, E1, n, W1, b1, W2, b2, fcw, fcb, out);
    run_graph(x2, e2, E2, n, W1, b1, W2, b2, fcw, fcb, out + D);
}

// round 4
// speedup vs baseline: 1.1277x; 1.0284x over previous
#include <cuda_runtime.h>
#include <cuda_fp16.h>
#include <cuda_bf16.h>

#define NMAX 100000
#define EMAX 1700000
#define D 64

// Scratch (allocation-free: __device__ globals). Index [graph] via offsets.
__device__ __half g_h[2 * NMAX * D];    // matmul output / gather source (fp16)
__device__ float  g_y[2 * NMAX * D];    // layer output (post relu, fp32)
__device__ int    g_deg[2 * NMAX];
__device__ float  g_dinv[2 * NMAX];
__device__ int    g_rowptr[2 * (NMAX + 1)];
__device__ int    g_fill[2 * NMAX];     // moving fill pointer for CSR build
__device__ int    g_col[2 * EMAX];
__device__ int    g_bsum[2 * 128];
__device__ int    g_boff[2 * 128];
__device__ float  g_sums[2 * D];

// ---------------------------------------------------------------------------
__global__ void zero_k(int n) {
    int i = blockIdx.x * blockDim.x + threadIdx.x;
    if (i < 2 * n) g_deg[i] = 0;
    if (i < 2 * D) g_sums[i] = 0.0f;
}

__global__ void degree_k(const int* __restrict__ e1, const int* __restrict__ e2,
                         int E1, int E2) {
    int g = blockIdx.y;
    int E = g ? E2 : E1;
    const int* dst = (g ? e2 : e1) + E;   // second half of edge_index = dst
    int i = blockIdx.x * blockDim.x + threadIdx.x;
    if (i < E) atomicAdd(&g_deg[g * NMAX + dst[i]], 1);
}

// ---- exclusive prefix scan of g_deg -> g_rowptr ---------------------------
__global__ void scan_block_k(int n) {
    __shared__ int s[1024];
    int g = blockIdx.y;
    int gid = blockIdx.x * 1024 + threadIdx.x;
    int v = (gid < n) ? g_deg[g * NMAX + gid] : 0;
    s[threadIdx.x] = v;
    __syncthreads();
#pragma unroll
    for (int off = 1; off < 1024; off <<= 1) {
        int t = 0;
        if (threadIdx.x >= off) t = s[threadIdx.x - off];
        __syncthreads();
        if (threadIdx.x >= off) s[threadIdx.x] += t;
        __syncthreads();
    }
    if (gid < n) g_rowptr[g * (NMAX + 1) + gid] = s[threadIdx.x] - v;  // exclusive
    if (threadIdx.x == 1023) g_bsum[g * 128 + blockIdx.x] = s[1023];
}

__global__ void scan_bsums_k(int nb) {
    __shared__ int s[128];
    int g = blockIdx.y;
    int v = (threadIdx.x < nb) ? g_bsum[g * 128 + threadIdx.x] : 0;
    s[threadIdx.x] = v;
    __syncthreads();
#pragma unroll
    for (int off = 1; off < 128; off <<= 1) {
        int t = 0;
        if (threadIdx.x >= off) t = s[threadIdx.x - off];
        __syncthreads();
        if (threadIdx.x >= off) s[threadIdx.x] += t;
        __syncthreads();
    }
    g_boff[g * 128 + threadIdx.x] = s[threadIdx.x] - v;  // exclusive
}

// rowptr += block offset; init fill ptr; dinv = rsqrt(deg+1)
__global__ void finalize_csr_k(int n, int E1, int E2) {
    int g = blockIdx.y;
    int gid = blockIdx.x * blockDim.x + threadIdx.x;
    if (gid < n) {
        int rp = g_rowptr[g * (NMAX + 1) + gid] + g_boff[g * 128 + (gid >> 10)];
        g_rowptr[g * (NMAX + 1) + gid] = rp;
        g_fill[g * NMAX + gid] = rp;
        g_dinv[g * NMAX + gid] = rsqrtf((float)g_deg[g * NMAX + gid] + 1.0f);
    }
    if (gid == n) g_rowptr[g * (NMAX + 1) + n] = g ? E2 : E1;
}

__global__ void fill_k(const int* __restrict__ e1, const int* __restrict__ e2,
                       int E1, int E2) {
    int g = blockIdx.y;
    int E = g ? E2 : E1;
    const int* ei = g ? e2 : e1;
    int e = blockIdx.x * blockDim.x + threadIdx.x;
    if (e >= E) return;
    int s = ei[e];         // src
    int d = ei[E + e];     // dst
    int slot = atomicAdd(&g_fill[g * NMAX + d], 1);
    g_col[g * EMAX + slot] = s;
}

// ---------------------------------------------------------------------------
// h = in @ W (fp16 out).  W[:,j] in 64 regs per thread; x row via broadcast LDG.
#define RPB 64
__global__ void matmul_k(const float* __restrict__ x1, const float* __restrict__ x2,
                         const float* __restrict__ W, int use_y, int n) {
    int g = blockIdx.y;
    int j = threadIdx.x & 63;
    int rg = threadIdx.x >> 6;  // 0..3
    const float* xin = use_y ? (g_y + (size_t)g * NMAX * D) : (g ? x2 : x1);
    __half* hout = g_h + (size_t)g * NMAX * D;

    float w[64];
#pragma unroll
    for (int k = 0; k < 64; k++) w[k] = W[k * 64 + j];  // coalesced over j

    int rend = min((blockIdx.x + 1) * RPB, n);
    for (int r = blockIdx.x * RPB + rg; r < rend; r += 4) {
        const float4* xv = reinterpret_cast<const float4*>(xin + (size_t)r * D);
        float acc = 0.0f;
#pragma unroll
        for (int k4 = 0; k4 < 16; k4++) {
            float4 t = xv[k4];
            acc += t.x * w[4 * k4 + 0];
            acc += t.y * w[4 * k4 + 1];
            acc += t.z * w[4 * k4 + 2];
            acc += t.w * w[4 * k4 + 3];
        }
        hout[(size_t)r * D + j] = __float2half_rn(acc);
    }
}

// ---------------------------------------------------------------------------
// Fused: y[d] = relu(b + dinv[d]^2*h[d] + sum_nb dinv[s]*dinv[d]*h[s])
// 8 lanes per node (16B fp16 gather each), neighbor loop unrolled x4 for MLP.
__device__ __forceinline__ void acc_row(float acc[8], const uint4* hv, int idx,
                                        int lane, float nm) {
    uint4 v = hv[idx * 8 + lane];
    const __half2* hp = reinterpret_cast<const __half2*>(&v);
#pragma unroll
    for (int q = 0; q < 4; q++) {
        float2 f = __half22float2(hp[q]);
        acc[2 * q + 0] += f.x * nm;
        acc[2 * q + 1] += f.y * nm;
    }
}

__global__ void aggregate_k(const float* __restrict__ b, int n, int do_pool) {
    __shared__ float s[64];
    int g = blockIdx.y;
    int tid = threadIdx.x;
    if (do_pool) {
        if (tid < 64) s[tid] = 0.0f;
        __syncthreads();
    }

    int row = blockIdx.x * 32 + (tid >> 3);
    int lane = tid & 7;
    float y[8];
#pragma unroll
    for (int q = 0; q < 8; q++) y[q] = 0.0f;

    if (row < n) {
        const uint4* hv = reinterpret_cast<const uint4*>(g_h + (size_t)g * NMAX * D);
        const float* dinv = g_dinv + g * NMAX;
        const int* col = g_col + (size_t)g * EMAX;
        const int* rowptr = g_rowptr + g * (NMAX + 1);

        float dd = dinv[row];
        float acc[8];
#pragma unroll
        for (int q = 0; q < 8; q++) acc[q] = 0.0f;
        acc_row(acc, hv, row, lane, dd * dd);   // self loop

        int p0 = rowptr[row];
        int p1 = rowptr[row + 1];
        int p = p0;
        for (; p + 4 <= p1; p += 4) {
            int i0 = col[p + 0], i1 = col[p + 1], i2 = col[p + 2], i3 = col[p + 3];
            float n0 = dd * dinv[i0], n1 = dd * dinv[i1];
            float n2 = dd * dinv[i2], n3 = dd * dinv[i3];
            acc_row(acc, hv, i0, lane, n0);
            acc_row(acc, hv, i1, lane, n1);
            acc_row(acc, hv, i2, lane, n2);
            acc_row(acc, hv, i3, lane, n3);
        }
        for (; p < p1; p++) {
            int i0 = col[p];
            acc_row(acc, hv, i0, lane, dd * dinv[i0]);
        }

        float* yout = g_y + (size_t)g * NMAX * D + (size_t)row * D + lane * 8;
        float4 o0, o1;
        const float4* bv = reinterpret_cast<const float4*>(b + lane * 8);
        float4 b0 = bv[0], b1 = bv[1];
        o0.x = fmaxf(acc[0] + b0.x, 0.f); o0.y = fmaxf(acc[1] + b0.y, 0.f);
        o0.z = fmaxf(acc[2] + b0.z, 0.f); o0.w = fmaxf(acc[3] + b0.w, 0.f);
        o1.x = fmaxf(acc[4] + b1.x, 0.f); o1.y = fmaxf(acc[5] + b1.y, 0.f);
        o1.z = fmaxf(acc[6] + b1.z, 0.f); o1.w = fmaxf(acc[7] + b1.w, 0.f);
        reinterpret_cast<float4*>(yout)[0] = o0;
        reinterpret_cast<float4*>(yout)[1] = o1;
        y[0] = o0.x; y[1] = o0.y; y[2] = o0.z; y[3] = o0.w;
        y[4] = o1.x; y[5] = o1.y; y[6] = o1.z; y[7] = o1.w;
    }

    if (do_pool) {
#pragma unroll
        for (int q = 0; q < 8; q++) atomicAdd(&s[lane * 8 + q], y[q]);
        __syncthreads();
        if (tid < 64) atomicAdd(&g_sums[g * 64 + tid], s[tid]);
    }
}

// out[g][j] = fc_b[j] + sum_k mean[g][k] * fc_w[j,k]
__global__ void fc_k(const float* __restrict__ fcw, const float* __restrict__ fcb,
                     float* __restrict__ out, float invn) {
    int g = threadIdx.x >> 6;
    int j = threadIdx.x & 63;
    if (threadIdx.x >= 128) return;
    float acc = fcb[j];
#pragma unroll 16
    for (int k = 0; k < D; k++)
        acc += (g_sums[g * 64 + k] * invn) * fcw[j * D + k];
    out[g * 64 + j] = acc;
}

// ---------------------------------------------------------------------------
extern "C" void kernel_launch(void* const* d_in, const int* in_sizes, int n_in,
                              void* d_out, int out_size) {
    const float* x1  = (const float*)d_in[0];
    const float* x2  = (const float*)d_in[1];
    const int*   e1  = (const int*)d_in[2];
    const int*   e2  = (const int*)d_in[3];
    const float* W1  = (const float*)d_in[4];
    const float* b1  = (const float*)d_in[5];
    const float* W2  = (const float*)d_in[6];
    const float* b2  = (const float*)d_in[7];
    const float* fcw = (const float*)d_in[8];
    const float* fcb = (const float*)d_in[9];

    int n  = in_sizes[0] / D;
    int E1 = in_sizes[2] / 2;
    int E2 = in_sizes[3] / 2;
    int Emax = max(E1, E2);
    float* out = (float*)d_out;

    const int T = 256;
    dim3 nBlk((2 * n + T - 1) / T);
    dim3 eBlk((Emax + T - 1) / T, 2);
    dim3 scanBlk((n + 1023) / 1024, 2);
    dim3 finBlk((n + T) / T, 2);
    dim3 mmBlk((n + RPB - 1) / RPB, 2);
    dim3 aggBlk((n + 31) / 32, 2);

    // degree + normalization + CSR (built once, reused by both layers)
    zero_k<<<nBlk, T>>>(n);
    degree_k<<<eBlk, T>>>(e1, e2, E1, E2);
    scan_block_k<<<scanBlk, 1024>>>(n);
    scan_bsums_k<<<dim3(1, 2), 128>>>((n + 1023) / 1024);
    finalize_csr_k<<<finBlk, T>>>(n, E1, E2);
    fill_k<<<eBlk, T>>>(e1, e2, E1, E2);

    // layer 1
    matmul_k<<<mmBlk, T>>>(x1, x2, W1, 0, n);
    aggregate_k<<<aggBlk, T>>>(b1, n, 0);

    // layer 2 (input = g_y); aggregation also does the mean-pool reduction
    matmul_k<<<mmBlk, T>>>(x1, x2, W2, 1, n);
    aggregate_k<<<aggBlk, T>>>(b2, n, 1);

    fc_k<<<1, 128>>>(fcw, fcb, out, 1.0f / (float)n);
}